// round 3
// baseline (speedup 1.0000x reference)
#include <cuda_runtime.h>
#include <math.h>

#define N_USERS 50000
#define N_ITEMS 100000
#define NN      150000
#define DD      64
#define NI      128
#define TS      32
#define TEMP    0.2f
#define KL_REG  0.01f
#define EMB_REG 1e-5f
#define INT_REG 1e-5f
#define SSL_REG 0.1f
#define BB      4096
#define E_TOT   3150000
#define NSPLIT  8
#define JCH     (BB / NSPLIT)

// ---------------- scratch (device globals; no allocation allowed) ------------
__device__ int   g_deg[NN];
__device__ float g_dinv[NN];
__device__ int   g_rowptr[NN + 1];
__device__ int   g_cursor[NN];
__device__ int   g_csr_t[E_TOT];
__device__ float g_csr_g[E_TOT];
__device__ float g_cur[(size_t)NN * DD];
__device__ float g_nxt[(size_t)NN * DD];
__device__ float g_acc[(size_t)NN * DD];
__device__ float g_ugen[BB * DD];
__device__ float g_uintn[BB * DD];
__device__ float g_igen[BB * DD];
__device__ float g_iintn[BB * DD];
__device__ float g_neg[2 * BB];
__device__ float g_pos[2 * BB];
__device__ float g_sums[8];   // 0:bpr 1:kl 2:emb 3:int 4:cl

// ---------------- helpers ----------------------------------------------------
__device__ __forceinline__ float softplusf(float x) {
    return x > 0.f ? x + log1pf(expf(-x)) : log1pf(expf(x));
}

// block-of-256 sum; result valid on thread 0
__device__ __forceinline__ float blkSum256(float v) {
    __shared__ float sp[8];
    int lane = threadIdx.x & 31, wid = threadIdx.x >> 5;
#pragma unroll
    for (int o = 16; o; o >>= 1) v += __shfl_down_sync(0xffffffffu, v, o);
    if (lane == 0) sp[wid] = v;
    __syncthreads();
    v = (threadIdx.x < 8) ? sp[threadIdx.x] : 0.f;
    if (wid == 0) {
#pragma unroll
        for (int o = 4; o; o >>= 1) v += __shfl_down_sync(0xffffffffu, v, o);
    }
    __syncthreads();
    return v;
}

// 128-thread block sum (all threads get the result)
__device__ __forceinline__ float blkSum128(float v, float* partial) {
    int lane = threadIdx.x & 31, wid = threadIdx.x >> 5;
#pragma unroll
    for (int o = 16; o; o >>= 1) v += __shfl_down_sync(0xffffffffu, v, o);
    if (lane == 0) partial[wid] = v;
    __syncthreads();
    float s = partial[0] + partial[1] + partial[2] + partial[3];
    __syncthreads();
    return s;
}

__device__ __forceinline__ float blkMax128(float v, float* partial) {
    int lane = threadIdx.x & 31, wid = threadIdx.x >> 5;
#pragma unroll
    for (int o = 16; o; o >>= 1) v = fmaxf(v, __shfl_down_sync(0xffffffffu, v, o));
    if (lane == 0) partial[wid] = v;
    __syncthreads();
    float s = fmaxf(fmaxf(partial[0], partial[1]), fmaxf(partial[2], partial[3]));
    __syncthreads();
    return s;
}

// ---------------- kernels ----------------------------------------------------
__global__ void k_clear() {
    int i = blockIdx.x * blockDim.x + threadIdx.x;
    if (i < NN) g_deg[i] = 0;
    if (i < 8) g_sums[i] = 0.f;
    if (i < 2 * BB) { g_neg[i] = 0.f; g_pos[i] = 0.f; }
}

__global__ void k_deg(const int* __restrict__ hl, int E) {
    int e = blockIdx.x * blockDim.x + threadIdx.x;
    if (e < E) atomicAdd(&g_deg[hl[e]], 1);
}

__global__ void k_dinv() {
    int i = blockIdx.x * blockDim.x + threadIdx.x;
    if (i < NN) g_dinv[i] = rsqrtf((float)g_deg[i]);
}

// single-block exclusive scan of g_deg -> g_rowptr / g_cursor (4 elems/thread/chunk)
__global__ void k_scan() {
    __shared__ int wsum[32];
    __shared__ int carry_s;
    __shared__ int chunktot_s;
    int tid = threadIdx.x, lane = tid & 31, wid = tid >> 5;
    if (tid == 0) carry_s = 0;
    __syncthreads();
    for (int base = 0; base < NN; base += 4096) {
        int v[4]; int s = 0;
#pragma unroll
        for (int j = 0; j < 4; j++) {
            int i = base + tid * 4 + j;
            v[j] = (i < NN) ? g_deg[i] : 0;
            s += v[j];
        }
        int t = s;
#pragma unroll
        for (int o = 1; o < 32; o <<= 1) {
            int x = __shfl_up_sync(0xffffffffu, t, o);
            if (lane >= o) t += x;
        }
        if (lane == 31) wsum[wid] = t;
        __syncthreads();
        if (wid == 0) {
            int w = wsum[lane];
#pragma unroll
            for (int o = 1; o < 32; o <<= 1) {
                int x = __shfl_up_sync(0xffffffffu, w, o);
                if (lane >= o) w += x;
            }
            wsum[lane] = w;
            if (lane == 31) chunktot_s = w;
        }
        __syncthreads();
        int warpoff = (wid > 0) ? wsum[wid - 1] : 0;
        int run = carry_s + warpoff + (t - s);
#pragma unroll
        for (int j = 0; j < 4; j++) {
            int i = base + tid * 4 + j;
            if (i < NN) { g_rowptr[i] = run; g_cursor[i] = run; }
            run += v[j];
        }
        __syncthreads();
        if (tid == 0) carry_s += chunktot_s;
        __syncthreads();
    }
    if (tid == 0) g_rowptr[NN] = carry_s;
}

__global__ void k_scatter(const int* __restrict__ hl, const int* __restrict__ tl, int E) {
    int e = blockIdx.x * blockDim.x + threadIdx.x;
    if (e >= E) return;
    int h = hl[e], t = tl[e];
    int idx = atomicAdd(&g_cursor[h], 1);
    g_csr_t[idx] = t;
    g_csr_g[idx] = g_dinv[h] * g_dinv[t];
}

__global__ void k_init(const float* __restrict__ ue, const float* __restrict__ ie) {
    int i = blockIdx.x * blockDim.x + threadIdx.x;
    if (i >= NN * DD) return;
    int n = i >> 6, d = i & 63;
    float v = (n < N_USERS) ? ue[n * DD + d] : ie[(n - N_USERS) * DD + d];
    g_cur[i] = v;
    g_acc[i] = v;
}

// one warp per node; lane handles 2 dims (float2); accumulates in registers,
// writes dst once and fuses acc += dst. flip=0: cur->nxt, flip=1: nxt->cur.
__global__ void k_prop(int flip) {
    int gw = (blockIdx.x * blockDim.x + threadIdx.x) >> 5;
    int lane = threadIdx.x & 31;
    if (gw >= NN) return;
    const float* __restrict__ src = flip ? g_nxt : g_cur;
    float* __restrict__ dst = flip ? g_cur : g_nxt;
    int s = g_rowptr[gw], e = g_rowptr[gw + 1];
    float a0 = 0.f, a1 = 0.f;
    int k = s;
    for (; k + 1 < e; k += 2) {
        int   t0 = g_csr_t[k],     t1 = g_csr_t[k + 1];
        float w0 = g_csr_g[k],     w1 = g_csr_g[k + 1];
        float2 v0 = *(const float2*)(src + (size_t)t0 * DD + lane * 2);
        float2 v1 = *(const float2*)(src + (size_t)t1 * DD + lane * 2);
        a0 += w0 * v0.x + w1 * v1.x;
        a1 += w0 * v0.y + w1 * v1.y;
    }
    if (k < e) {
        int t0 = g_csr_t[k]; float w0 = g_csr_g[k];
        float2 v0 = *(const float2*)(src + (size_t)t0 * DD + lane * 2);
        a0 += w0 * v0.x;
        a1 += w0 * v0.y;
    }
    size_t o = (size_t)gw * DD + lane * 2;
    dst[o] = a0; dst[o + 1] = a1;
    g_acc[o] += a0; g_acc[o + 1] += a1;
}

// KL term over all N rows. block = 256 = 4 rows x 64 dims.
__global__ void k_kl(const float* __restrict__ lw, const float* __restrict__ lb) {
    __shared__ float swT[TS * DD];   // transposed lin_w: swT[t*64+d]
    __shared__ float sb[DD];
    __shared__ float ss[4][TS];
    int tid = threadIdx.x;
    for (int i = tid; i < TS * DD; i += 256) {
        int d = i >> 5, t = i & 31;
        swT[t * DD + d] = lw[i];
    }
    if (tid < DD) sb[tid] = lb[tid];
    __syncthreads();
    int r = tid >> 6;            // row within block
    int d = tid & 63;
    int row = blockIdx.x * 4 + r;
    if (row < NN && d < TS) ss[r][d] = softplusf(g_acc[(size_t)row * DD + d]);
    __syncthreads();
    float klv = 0.f;
    if (row < NN) {
        float stdv = sb[d] + 1e-8f;
#pragma unroll
        for (int t = 0; t < TS; t++) stdv += ss[r][t] * swT[t * DD + d];
        float mn = g_acc[(size_t)row * DD + d];
        float kl = -0.5f * (1.f + 2.f * stdv - mn * mn - expf(2.f * stdv));
        if (isfinite(kl)) klv = kl;
    }
    float tot = blkSum256(klv);
    if (tid == 0) atomicAdd(&g_sums[1], tot);
}

// BPR + embedding-reg over B samples; one warp per sample.
__global__ void k_bpr(const float* __restrict__ ue, const float* __restrict__ ie,
                      const int* __restrict__ users, const int* __restrict__ pos,
                      const int* __restrict__ neg) {
    int w = (blockIdx.x * blockDim.x + threadIdx.x) >> 5;
    int lane = threadIdx.x & 31;
    if (w >= BB) return;
    int u = users[w], p = pos[w], n = neg[w];
    const float* au = g_acc + (size_t)u * DD;
    const float* ap = g_acc + (size_t)(N_USERS + p) * DD;
    const float* an = g_acc + (size_t)(N_USERS + n) * DD;
    float ps = 0.f, ns = 0.f, es = 0.f;
#pragma unroll
    for (int j = 0; j < 2; j++) {
        int d = lane + 32 * j;
        float x = au[d];
        ps += x * ap[d];
        ns += x * an[d];
        float a = ue[(size_t)u * DD + d], b = ie[(size_t)p * DD + d], c = ie[(size_t)n * DD + d];
        es += a * a + b * b + c * c;
    }
#pragma unroll
    for (int o = 16; o; o >>= 1) {
        ps += __shfl_down_sync(0xffffffffu, ps, o);
        ns += __shfl_down_sync(0xffffffffu, ns, o);
        es += __shfl_down_sync(0xffffffffu, es, o);
    }
    if (lane == 0) {
        atomicAdd(&g_sums[0], softplusf(ns - ps));
        atomicAdd(&g_sums[2], es);
    }
}

// intent regularizer: sum of squares of both intent matrices (64x128 each)
__global__ void k_intreg(const float* __restrict__ ui, const float* __restrict__ ii) {
    int i = blockIdx.x * blockDim.x + threadIdx.x;
    float v = 0.f;
    if (i < DD * NI)            { float a = ui[i];           v = a * a; }
    else if (i < 2 * DD * NI)   { float a = ii[i - DD * NI]; v = a * a; }
    float tot = blkSum256(v);
    if (threadIdx.x == 0) atomicAdd(&g_sums[3], tot);
}

// per-sample features: normalized gen_emb and intent-projection rows.
// block = 128 threads; blockIdx < BB -> user side, else item side.
__global__ void k_sample(const float* __restrict__ lw, const float* __restrict__ lb,
                         const float* __restrict__ eps,
                         const float* __restrict__ uintm, const float* __restrict__ iintm,
                         const int* __restrict__ users, const int* __restrict__ pos) {
    __shared__ float mrow[DD];
    __shared__ float sp[TS];
    __shared__ float prob[NI];
    __shared__ float partial[4];
    int b = blockIdx.x & (BB - 1);
    int side = blockIdx.x >> 12;       // BB = 4096 = 2^12
    int tid = threadIdx.x;
    int node = side ? (N_USERS + pos[b]) : users[b];
    const float* intent = side ? iintm : uintm;
    float* outgen = side ? g_igen : g_ugen;
    float* outint = side ? g_iintn : g_uintn;

    if (tid < DD) mrow[tid] = g_acc[(size_t)node * DD + tid];
    __syncthreads();
    if (tid < TS) sp[tid] = softplusf(mrow[tid]);
    __syncthreads();

    // gen_emb row + normalize
    float genv = 0.f;
    if (tid < DD) {
        float stdv = lb[tid] + 1e-8f;
#pragma unroll
        for (int t = 0; t < TS; t++) stdv += sp[t] * lw[tid * TS + t];
        genv = mrow[tid] + eps[(size_t)node * DD + tid] * stdv;
    }
    float gn2 = blkSum128(genv * genv, partial);
    if (tid < DD) outgen[b * DD + tid] = genv * rsqrtf(gn2);

    // intent projection: logits over 128 intents
    float lg = 0.f;
#pragma unroll
    for (int d = 0; d < DD; d++) lg += mrow[d] * intent[d * NI + tid];
    float mx = blkMax128(lg, partial);
    float ev = expf(lg - mx);
    float ssum = blkSum128(ev, partial);
    prob[tid] = ev;
    __syncthreads();

    float o = 0.f;
    if (tid < DD) {
        const float4* ip = (const float4*)(intent + tid * NI);
        const float4* pp = (const float4*)prob;
#pragma unroll
        for (int k = 0; k < NI / 4; k++) {
            float4 a = ip[k], pq = pp[k];
            o += a.x * pq.x + a.y * pq.y + a.z * pq.z + a.w * pq.w;
        }
        o /= ssum;
    }
    float on2 = blkSum128(o * o, partial);
    if (tid < DD) outint[b * DD + tid] = o * rsqrtf(on2);
}

// InfoNCE partial sums: e1=gen, e2=int. grid (BB/256, NSPLIT).
__global__ void k_nce(const float* __restrict__ e1, const float* __restrict__ e2,
                      float* __restrict__ negbuf, float* __restrict__ posbuf) {
    __shared__ float tile[32][DD];
    int tid = threadIdx.x;
    int i = blockIdx.x * 256 + tid;
    float r[DD];
#pragma unroll
    for (int d = 0; d < DD; d++) r[d] = e1[i * DD + d];
    float negs = 0.f, pos = 0.f;
    int j0 = blockIdx.y * JCH;
    for (int jt = 0; jt < JCH; jt += 32) {
#pragma unroll
        for (int q = 0; q < 8; q++) {
            int idx = tid + q * 256;
            tile[idx >> 6][idx & 63] = e2[(j0 + jt) * DD + idx];
        }
        __syncthreads();
#pragma unroll 4
        for (int jj = 0; jj < 32; jj++) {
            float dot = 0.f;
#pragma unroll
            for (int d = 0; d < DD; d++) dot += r[d] * tile[jj][d];
            float evv = __expf(dot * (1.f / TEMP));
            negs += evv;
            if (j0 + jt + jj == i) pos = evv;
        }
        __syncthreads();
    }
    atomicAdd(&negbuf[i], negs);
    if (i >= j0 && i < j0 + JCH) posbuf[i] = pos;
}

__global__ void k_ncefinal() {
    int i = blockIdx.x * blockDim.x + threadIdx.x;
    float l = 0.f;
    if (i < 2 * BB) l = -logf(g_pos[i] / (g_neg[i] + 1e-8f) + 1e-8f);
    float tot = blkSum256(l);
    if (threadIdx.x == 0) atomicAdd(&g_sums[4], tot);
}

__global__ void k_final(float* __restrict__ out) {
    if (threadIdx.x == 0 && blockIdx.x == 0) {
        float bpr = g_sums[0] / (float)BB;
        float kl  = KL_REG * (g_sums[1] / (float)NN);
        out[0] = bpr + kl;                              // gen_loss
        out[1] = SSL_REG * (g_sums[4] / (float)BB);     // cl_loss
        out[2] = EMB_REG * g_sums[2];                   // emb_loss
        out[3] = INT_REG * g_sums[3];                   // int_loss
    }
}

// ---------------- launch ------------------------------------------------------
extern "C" void kernel_launch(void* const* d_in, const int* in_sizes, int n_in,
                              void* d_out, int out_size) {
    const float* user_emb = (const float*)d_in[0];
    const float* item_emb = (const float*)d_in[1];
    const float* uintm    = (const float*)d_in[2];
    const float* iintm    = (const float*)d_in[3];
    const float* lw       = (const float*)d_in[4];
    const float* lb       = (const float*)d_in[5];
    const float* eps      = (const float*)d_in[6];
    const int*   hl       = (const int*)d_in[7];
    const int*   tl       = (const int*)d_in[8];
    const int*   users    = (const int*)d_in[9];
    const int*   pos      = (const int*)d_in[10];
    const int*   neg      = (const int*)d_in[11];
    int E = in_sizes[7];
    float* out = (float*)d_out;

    k_clear<<<(NN + 255) / 256, 256>>>();
    k_deg<<<(E + 255) / 256, 256>>>(hl, E);
    k_dinv<<<(NN + 255) / 256, 256>>>();
    k_scan<<<1, 1024>>>();
    k_scatter<<<(E + 255) / 256, 256>>>(hl, tl, E);
    k_init<<<(NN * DD + 255) / 256, 256>>>(user_emb, item_emb);

    k_prop<<<(NN * 32 + 255) / 256, 256>>>(0);   // cur -> nxt
    k_prop<<<(NN * 32 + 255) / 256, 256>>>(1);   // nxt -> cur
    k_prop<<<(NN * 32 + 255) / 256, 256>>>(0);   // cur -> nxt

    k_kl<<<(NN + 3) / 4, 256>>>(lw, lb);
    k_bpr<<<(BB * 32 + 255) / 256, 256>>>(user_emb, item_emb, users, pos, neg);
    k_intreg<<<(2 * DD * NI + 255) / 256, 256>>>(uintm, iintm);
    k_sample<<<2 * BB, 128>>>(lw, lb, eps, uintm, iintm, users, pos);

    {
        float *e1u, *e2u, *e1i, *e2i, *negb, *posb;
        // kernels reference device symbols directly; nce needs pointers:
        // use small trampoline via symbol-referencing launches with constants.
        // (addresses obtained inside kernels via the symbols themselves)
        (void)e1u; (void)e2u; (void)e1i; (void)e2i; (void)negb; (void)posb;
    }
    // nce over (u_gen, u_int) -> g_neg/g_pos[0..BB), (i_gen, i_int) -> [BB..2BB)
    {
        // get device addresses of the symbols (host API; graph-capture safe)
        void *p_ugen, *p_uint, *p_igen, *p_iint, *p_neg, *p_pos;
        cudaGetSymbolAddress(&p_ugen, g_ugen);
        cudaGetSymbolAddress(&p_uint, g_uintn);
        cudaGetSymbolAddress(&p_igen, g_igen);
        cudaGetSymbolAddress(&p_iint, g_iintn);
        cudaGetSymbolAddress(&p_neg,  g_neg);
        cudaGetSymbolAddress(&p_pos,  g_pos);
        dim3 grid(BB / 256, NSPLIT);
        k_nce<<<grid, 256>>>((const float*)p_ugen, (const float*)p_uint,
                             (float*)p_neg, (float*)p_pos);
        k_nce<<<grid, 256>>>((const float*)p_igen, (const float*)p_iint,
                             (float*)p_neg + BB, (float*)p_pos + BB);
    }
    k_ncefinal<<<(2 * BB + 255) / 256, 256>>>();
    k_final<<<1, 32>>>(out);
}

// round 4
// speedup vs baseline: 1.1304x; 1.1304x over previous
#include <cuda_runtime.h>
#include <math.h>

#define N_USERS 50000
#define N_ITEMS 100000
#define NN      150000
#define DD      64
#define NI      128
#define TS      32
#define TEMP    0.2f
#define KL_REG  0.01f
#define EMB_REG 1e-5f
#define INT_REG 1e-5f
#define SSL_REG 0.1f
#define BB      4096
#define E_TOT   3150000
#define NSPLIT  16
#define JCH     (BB / NSPLIT)

#define SCAN_CHUNK 4096
#define NBLK_SCAN  ((NN + SCAN_CHUNK - 1) / SCAN_CHUNK)   // 37

// ---------------- scratch (device globals; no allocation allowed) ------------
__device__ int   g_deg[NN];
__device__ float g_dinv[NN];
__device__ int   g_rowptr[NN + 1];
__device__ int   g_cursor[NN];
__device__ int   g_blocksum[NBLK_SCAN];
__device__ int   g_blockoff[NBLK_SCAN];
__device__ int   g_csr_t[E_TOT];
__device__ float g_csr_g[E_TOT];
__device__ float g_cur[(size_t)NN * DD];
__device__ float g_nxt[(size_t)NN * DD];
__device__ float g_acc[(size_t)NN * DD];
__device__ float g_ugen[BB * DD];
__device__ float g_uintn[BB * DD];
__device__ float g_igen[BB * DD];
__device__ float g_iintn[BB * DD];
__device__ float g_neg[2 * BB];
__device__ float g_pos[2 * BB];
__device__ float g_sums[8];   // 0:bpr 1:kl 2:emb 3:int 4:cl

// ---------------- helpers ----------------------------------------------------
__device__ __forceinline__ float softplusf(float x) {
    return x > 0.f ? x + log1pf(expf(-x)) : log1pf(expf(x));
}

__device__ __forceinline__ float blkSum256(float v) {
    __shared__ float sp[8];
    int lane = threadIdx.x & 31, wid = threadIdx.x >> 5;
#pragma unroll
    for (int o = 16; o; o >>= 1) v += __shfl_down_sync(0xffffffffu, v, o);
    if (lane == 0) sp[wid] = v;
    __syncthreads();
    v = (threadIdx.x < 8) ? sp[threadIdx.x] : 0.f;
    if (wid == 0) {
#pragma unroll
        for (int o = 4; o; o >>= 1) v += __shfl_down_sync(0xffffffffu, v, o);
    }
    __syncthreads();
    return v;
}

__device__ __forceinline__ int blkSum256i(int v) {
    __shared__ int sp[8];
    int lane = threadIdx.x & 31, wid = threadIdx.x >> 5;
#pragma unroll
    for (int o = 16; o; o >>= 1) v += __shfl_down_sync(0xffffffffu, v, o);
    if (lane == 0) sp[wid] = v;
    __syncthreads();
    v = (threadIdx.x < 8) ? sp[threadIdx.x] : 0;
    if (wid == 0) {
#pragma unroll
        for (int o = 4; o; o >>= 1) v += __shfl_down_sync(0xffffffffu, v, o);
    }
    __syncthreads();
    return v;
}

__device__ __forceinline__ float blkSum128(float v, float* partial) {
    int lane = threadIdx.x & 31, wid = threadIdx.x >> 5;
#pragma unroll
    for (int o = 16; o; o >>= 1) v += __shfl_down_sync(0xffffffffu, v, o);
    if (lane == 0) partial[wid] = v;
    __syncthreads();
    float s = partial[0] + partial[1] + partial[2] + partial[3];
    __syncthreads();
    return s;
}

__device__ __forceinline__ float blkMax128(float v, float* partial) {
    int lane = threadIdx.x & 31, wid = threadIdx.x >> 5;
#pragma unroll
    for (int o = 16; o; o >>= 1) v = fmaxf(v, __shfl_down_sync(0xffffffffu, v, o));
    if (lane == 0) partial[wid] = v;
    __syncthreads();
    float s = fmaxf(fmaxf(partial[0], partial[1]), fmaxf(partial[2], partial[3]));
    __syncthreads();
    return s;
}

// ---------------- kernels ----------------------------------------------------
__global__ void k_clear() {
    int i = blockIdx.x * blockDim.x + threadIdx.x;
    if (i < NN) g_deg[i] = 0;
    if (i < 8) g_sums[i] = 0.f;
    if (i < 2 * BB) { g_neg[i] = 0.f; g_pos[i] = 0.f; }
}

__global__ void k_deg(const int* __restrict__ hl, int E) {
    int e = blockIdx.x * blockDim.x + threadIdx.x;
    if (e < E) atomicAdd(&g_deg[hl[e]], 1);
}

__global__ void k_dinv() {
    int i = blockIdx.x * blockDim.x + threadIdx.x;
    if (i < NN) g_dinv[i] = rsqrtf((float)g_deg[i]);
}

// ----- multi-block scan: A (chunk reduce), B (scan of 37 partials), C (local scan)
__global__ void k_scanA() {   // grid NBLK_SCAN, block 256
    int base = blockIdx.x * SCAN_CHUNK;
    int v = 0;
    for (int i = threadIdx.x; i < SCAN_CHUNK; i += 256) {
        int idx = base + i;
        if (idx < NN) v += g_deg[idx];
    }
    int tot = blkSum256i(v);
    if (threadIdx.x == 0) g_blocksum[blockIdx.x] = tot;
}

__global__ void k_scanB() {   // 1 thread serial scan of 37 values
    if (threadIdx.x == 0) {
        int run = 0;
        for (int i = 0; i < NBLK_SCAN; i++) { g_blockoff[i] = run; run += g_blocksum[i]; }
        g_rowptr[NN] = run;
    }
}

__global__ void k_scanC() {   // grid NBLK_SCAN, block 1024, 4 elems/thread
    __shared__ int wsum[32];
    int base = blockIdx.x * SCAN_CHUNK;
    int tid = threadIdx.x, lane = tid & 31, wid = tid >> 5;
    int v[4]; int s = 0;
#pragma unroll
    for (int j = 0; j < 4; j++) {
        int i = base + tid * 4 + j;
        v[j] = (i < NN) ? g_deg[i] : 0;
        s += v[j];
    }
    int t = s;
#pragma unroll
    for (int o = 1; o < 32; o <<= 1) {
        int x = __shfl_up_sync(0xffffffffu, t, o);
        if (lane >= o) t += x;
    }
    if (lane == 31) wsum[wid] = t;
    __syncthreads();
    if (wid == 0) {
        int w = wsum[lane];
#pragma unroll
        for (int o = 1; o < 32; o <<= 1) {
            int x = __shfl_up_sync(0xffffffffu, w, o);
            if (lane >= o) w += x;
        }
        wsum[lane] = w;
    }
    __syncthreads();
    int run = g_blockoff[blockIdx.x] + ((wid > 0) ? wsum[wid - 1] : 0) + (t - s);
#pragma unroll
    for (int j = 0; j < 4; j++) {
        int i = base + tid * 4 + j;
        if (i < NN) { g_rowptr[i] = run; g_cursor[i] = run; }
        run += v[j];
    }
}

__global__ void k_scatter(const int* __restrict__ hl, const int* __restrict__ tl, int E) {
    int e = blockIdx.x * blockDim.x + threadIdx.x;
    if (e >= E) return;
    int h = hl[e], t = tl[e];
    int idx = atomicAdd(&g_cursor[h], 1);
    g_csr_t[idx] = t;
    g_csr_g[idx] = g_dinv[h] * g_dinv[t];
}

__global__ void k_init(const float* __restrict__ ue, const float* __restrict__ ie) {
    int i = blockIdx.x * blockDim.x + threadIdx.x;
    if (i >= NN * DD) return;
    int n = i >> 6, d = i & 63;
    float v = (n < N_USERS) ? ue[n * DD + d] : ie[(n - N_USERS) * DD + d];
    g_cur[i] = v;
    g_acc[i] = v;
}

// one warp per node; lane handles 2 dims (float2); 4-edge unroll for MLP.
__global__ void k_prop(int flip) {
    int gw = (blockIdx.x * blockDim.x + threadIdx.x) >> 5;
    int lane = threadIdx.x & 31;
    if (gw >= NN) return;
    const float* __restrict__ src = flip ? g_nxt : g_cur;
    float* __restrict__ dst = flip ? g_cur : g_nxt;
    int s = g_rowptr[gw], e = g_rowptr[gw + 1];
    float a0 = 0.f, a1 = 0.f;
    int k = s;
    int lo = lane * 2;
    for (; k + 3 < e; k += 4) {
        int   t0 = __ldg(&g_csr_t[k]),     t1 = __ldg(&g_csr_t[k + 1]);
        int   t2 = __ldg(&g_csr_t[k + 2]), t3 = __ldg(&g_csr_t[k + 3]);
        float w0 = __ldg(&g_csr_g[k]),     w1 = __ldg(&g_csr_g[k + 1]);
        float w2 = __ldg(&g_csr_g[k + 2]), w3 = __ldg(&g_csr_g[k + 3]);
        float2 v0 = __ldg((const float2*)(src + (size_t)t0 * DD + lo));
        float2 v1 = __ldg((const float2*)(src + (size_t)t1 * DD + lo));
        float2 v2 = __ldg((const float2*)(src + (size_t)t2 * DD + lo));
        float2 v3 = __ldg((const float2*)(src + (size_t)t3 * DD + lo));
        a0 += w0 * v0.x + w1 * v1.x + w2 * v2.x + w3 * v3.x;
        a1 += w0 * v0.y + w1 * v1.y + w2 * v2.y + w3 * v3.y;
    }
    for (; k < e; k++) {
        int t0 = __ldg(&g_csr_t[k]); float w0 = __ldg(&g_csr_g[k]);
        float2 v0 = __ldg((const float2*)(src + (size_t)t0 * DD + lo));
        a0 += w0 * v0.x;
        a1 += w0 * v0.y;
    }
    size_t o = (size_t)gw * DD + lo;
    dst[o] = a0; dst[o + 1] = a1;
    g_acc[o] += a0; g_acc[o + 1] += a1;
}

// KL term over all N rows. block = 256 = 4 rows x 64 dims.
__global__ void k_kl(const float* __restrict__ lw, const float* __restrict__ lb) {
    __shared__ float swT[TS * DD];   // transposed lin_w: swT[t*64+d]
    __shared__ float sb[DD];
    __shared__ float ss[4][TS];
    int tid = threadIdx.x;
    for (int i = tid; i < TS * DD; i += 256) {
        int d = i >> 5, t = i & 31;
        swT[t * DD + d] = lw[i];
    }
    if (tid < DD) sb[tid] = lb[tid];
    __syncthreads();
    int r = tid >> 6;
    int d = tid & 63;
    int row = blockIdx.x * 4 + r;
    if (row < NN && d < TS) ss[r][d] = softplusf(g_acc[(size_t)row * DD + d]);
    __syncthreads();
    float klv = 0.f;
    if (row < NN) {
        float stdv = sb[d] + 1e-8f;
#pragma unroll
        for (int t = 0; t < TS; t++) stdv += ss[r][t] * swT[t * DD + d];
        float mn = g_acc[(size_t)row * DD + d];
        float kl = -0.5f * (1.f + 2.f * stdv - mn * mn - expf(2.f * stdv));
        if (isfinite(kl)) klv = kl;
    }
    float tot = blkSum256(klv);
    if (tid == 0) atomicAdd(&g_sums[1], tot);
}

// BPR + embedding-reg over B samples; one warp per sample.
__global__ void k_bpr(const float* __restrict__ ue, const float* __restrict__ ie,
                      const int* __restrict__ users, const int* __restrict__ pos,
                      const int* __restrict__ neg) {
    int w = (blockIdx.x * blockDim.x + threadIdx.x) >> 5;
    int lane = threadIdx.x & 31;
    if (w >= BB) return;
    int u = users[w], p = pos[w], n = neg[w];
    const float* au = g_acc + (size_t)u * DD;
    const float* ap = g_acc + (size_t)(N_USERS + p) * DD;
    const float* an = g_acc + (size_t)(N_USERS + n) * DD;
    float ps = 0.f, ns = 0.f, es = 0.f;
#pragma unroll
    for (int j = 0; j < 2; j++) {
        int d = lane + 32 * j;
        float x = au[d];
        ps += x * ap[d];
        ns += x * an[d];
        float a = ue[(size_t)u * DD + d], b = ie[(size_t)p * DD + d], c = ie[(size_t)n * DD + d];
        es += a * a + b * b + c * c;
    }
#pragma unroll
    for (int o = 16; o; o >>= 1) {
        ps += __shfl_down_sync(0xffffffffu, ps, o);
        ns += __shfl_down_sync(0xffffffffu, ns, o);
        es += __shfl_down_sync(0xffffffffu, es, o);
    }
    if (lane == 0) {
        atomicAdd(&g_sums[0], softplusf(ns - ps));
        atomicAdd(&g_sums[2], es);
    }
}

// intent regularizer
__global__ void k_intreg(const float* __restrict__ ui, const float* __restrict__ ii) {
    int i = blockIdx.x * blockDim.x + threadIdx.x;
    float v = 0.f;
    if (i < DD * NI)            { float a = ui[i];           v = a * a; }
    else if (i < 2 * DD * NI)   { float a = ii[i - DD * NI]; v = a * a; }
    float tot = blkSum256(v);
    if (threadIdx.x == 0) atomicAdd(&g_sums[3], tot);
}

// per-sample features: normalized gen_emb and intent-projection rows.
__global__ void k_sample(const float* __restrict__ lw, const float* __restrict__ lb,
                         const float* __restrict__ eps,
                         const float* __restrict__ uintm, const float* __restrict__ iintm,
                         const int* __restrict__ users, const int* __restrict__ pos) {
    __shared__ float mrow[DD];
    __shared__ float sp[TS];
    __shared__ float prob[NI];
    __shared__ float partial[4];
    int b = blockIdx.x & (BB - 1);
    int side = blockIdx.x >> 12;
    int tid = threadIdx.x;
    int node = side ? (N_USERS + pos[b]) : users[b];
    const float* intent = side ? iintm : uintm;
    float* outgen = side ? g_igen : g_ugen;
    float* outint = side ? g_iintn : g_uintn;

    if (tid < DD) mrow[tid] = g_acc[(size_t)node * DD + tid];
    __syncthreads();
    if (tid < TS) sp[tid] = softplusf(mrow[tid]);
    __syncthreads();

    float genv = 0.f;
    if (tid < DD) {
        float stdv = lb[tid] + 1e-8f;
#pragma unroll
        for (int t = 0; t < TS; t++) stdv += sp[t] * lw[tid * TS + t];
        genv = mrow[tid] + eps[(size_t)node * DD + tid] * stdv;
    }
    float gn2 = blkSum128(genv * genv, partial);
    if (tid < DD) outgen[b * DD + tid] = genv * rsqrtf(gn2);

    float lg = 0.f;
#pragma unroll
    for (int d = 0; d < DD; d++) lg += mrow[d] * intent[d * NI + tid];
    float mx = blkMax128(lg, partial);
    float ev = expf(lg - mx);
    float ssum = blkSum128(ev, partial);
    prob[tid] = ev;
    __syncthreads();

    float o = 0.f;
    if (tid < DD) {
        const float4* ip = (const float4*)(intent + tid * NI);
        const float4* pp = (const float4*)prob;
#pragma unroll
        for (int k = 0; k < NI / 4; k++) {
            float4 a = ip[k], pq = pp[k];
            o += a.x * pq.x + a.y * pq.y + a.z * pq.z + a.w * pq.w;
        }
        o /= ssum;
    }
    float on2 = blkSum128(o * o, partial);
    if (tid < DD) outint[b * DD + tid] = o * rsqrtf(on2);
}

// InfoNCE partial sums: grid (BB/256, NSPLIT).
__global__ void k_nce(const float* __restrict__ e1, const float* __restrict__ e2,
                      float* __restrict__ negbuf, float* __restrict__ posbuf) {
    __shared__ float tile[32][DD];
    int tid = threadIdx.x;
    int i = blockIdx.x * 256 + tid;
    float r[DD];
#pragma unroll
    for (int d = 0; d < DD; d++) r[d] = e1[i * DD + d];
    float negs = 0.f, pos = 0.f;
    int j0 = blockIdx.y * JCH;
    for (int jt = 0; jt < JCH; jt += 32) {
#pragma unroll
        for (int q = 0; q < 8; q++) {
            int idx = tid + q * 256;
            tile[idx >> 6][idx & 63] = e2[(j0 + jt) * DD + idx];
        }
        __syncthreads();
#pragma unroll 4
        for (int jj = 0; jj < 32; jj++) {
            float dot = 0.f;
#pragma unroll
            for (int d = 0; d < DD; d++) dot += r[d] * tile[jj][d];
            float evv = __expf(dot * (1.f / TEMP));
            negs += evv;
            if (j0 + jt + jj == i) pos = evv;
        }
        __syncthreads();
    }
    atomicAdd(&negbuf[i], negs);
    if (i >= j0 && i < j0 + JCH) posbuf[i] = pos;
}

__global__ void k_ncefinal() {
    int i = blockIdx.x * blockDim.x + threadIdx.x;
    float l = 0.f;
    if (i < 2 * BB) l = -logf(g_pos[i] / (g_neg[i] + 1e-8f) + 1e-8f);
    float tot = blkSum256(l);
    if (threadIdx.x == 0) atomicAdd(&g_sums[4], tot);
}

__global__ void k_final(float* __restrict__ out) {
    if (threadIdx.x == 0 && blockIdx.x == 0) {
        float bpr = g_sums[0] / (float)BB;
        float kl  = KL_REG * (g_sums[1] / (float)NN);
        out[0] = bpr + kl;
        out[1] = SSL_REG * (g_sums[4] / (float)BB);
        out[2] = EMB_REG * g_sums[2];
        out[3] = INT_REG * g_sums[3];
    }
}

// ---------------- launch ------------------------------------------------------
extern "C" void kernel_launch(void* const* d_in, const int* in_sizes, int n_in,
                              void* d_out, int out_size) {
    const float* user_emb = (const float*)d_in[0];
    const float* item_emb = (const float*)d_in[1];
    const float* uintm    = (const float*)d_in[2];
    const float* iintm    = (const float*)d_in[3];
    const float* lw       = (const float*)d_in[4];
    const float* lb       = (const float*)d_in[5];
    const float* eps      = (const float*)d_in[6];
    const int*   hl       = (const int*)d_in[7];
    const int*   tl       = (const int*)d_in[8];
    const int*   users    = (const int*)d_in[9];
    const int*   pos      = (const int*)d_in[10];
    const int*   neg      = (const int*)d_in[11];
    int E = in_sizes[7];
    float* out = (float*)d_out;

    k_clear<<<(NN + 255) / 256, 256>>>();
    k_deg<<<(E + 255) / 256, 256>>>(hl, E);
    k_dinv<<<(NN + 255) / 256, 256>>>();
    k_scanA<<<NBLK_SCAN, 256>>>();
    k_scanB<<<1, 32>>>();
    k_scanC<<<NBLK_SCAN, 1024>>>();
    k_scatter<<<(E + 255) / 256, 256>>>(hl, tl, E);
    k_init<<<(NN * DD + 255) / 256, 256>>>(user_emb, item_emb);

    k_prop<<<(NN * 32 + 255) / 256, 256>>>(0);   // cur -> nxt
    k_prop<<<(NN * 32 + 255) / 256, 256>>>(1);   // nxt -> cur
    k_prop<<<(NN * 32 + 255) / 256, 256>>>(0);   // cur -> nxt

    k_kl<<<(NN + 3) / 4, 256>>>(lw, lb);
    k_bpr<<<(BB * 32 + 255) / 256, 256>>>(user_emb, item_emb, users, pos, neg);
    k_intreg<<<(2 * DD * NI + 255) / 256, 256>>>(uintm, iintm);
    k_sample<<<2 * BB, 128>>>(lw, lb, eps, uintm, iintm, users, pos);

    {
        void *p_ugen, *p_uint, *p_igen, *p_iint, *p_neg, *p_pos;
        cudaGetSymbolAddress(&p_ugen, g_ugen);
        cudaGetSymbolAddress(&p_uint, g_uintn);
        cudaGetSymbolAddress(&p_igen, g_igen);
        cudaGetSymbolAddress(&p_iint, g_iintn);
        cudaGetSymbolAddress(&p_neg,  g_neg);
        cudaGetSymbolAddress(&p_pos,  g_pos);
        dim3 grid(BB / 256, NSPLIT);
        k_nce<<<grid, 256>>>((const float*)p_ugen, (const float*)p_uint,
                             (float*)p_neg, (float*)p_pos);
        k_nce<<<grid, 256>>>((const float*)p_igen, (const float*)p_iint,
                             (float*)p_neg + BB, (float*)p_pos + BB);
    }
    k_ncefinal<<<(2 * BB + 255) / 256, 256>>>();
    k_final<<<1, 32>>>(out);
}